// round 1
// baseline (speedup 1.0000x reference)
#include <cuda_runtime.h>

// Chain state: 4-channel fields only. h1 ping-pong (2 buffers), h2 stored per block
// for the final accumulation kernel.
__device__ float g_h1[2][16][4][64][64];   //  2.1 MB
__device__ float g_h2[32][16][4][64][64];  // 33.6 MB

// ---------------------------------------------------------------------------
// k0: h1_0 = relu(W1_0 @ x + b1_0).   x: [16,256,64,64].
// Grid 256 CTAs (16 images x 16 row-groups of 4 rows), 256 threads, 1 px each.
// ---------------------------------------------------------------------------
__global__ __launch_bounds__(256) void k0_kernel(const float* __restrict__ x,
                                                 const float* __restrict__ w1,
                                                 const float* __restrict__ b1) {
    __shared__ float4 sW1T[256];   // [c] -> (W1[0][c],W1[1][c],W1[2][c],W1[3][c])
    __shared__ float  sB1[4];
    int tid = threadIdx.x;
    if (tid < 4) sB1[tid] = b1[tid];
    sW1T[tid] = make_float4(w1[tid], w1[256 + tid], w1[512 + tid], w1[768 + tid]);
    __syncthreads();

    int n  = blockIdx.x >> 4;
    int yg = blockIdx.x & 15;
    int px = tid & 63;
    int y  = yg * 4 + (tid >> 6);

    const float* xp = x + (size_t)n * 256 * 4096 + y * 64 + px;
    float a0 = sB1[0], a1 = sB1[1], a2 = sB1[2], a3 = sB1[3];
#pragma unroll 8
    for (int c = 0; c < 256; c++) {
        float  xv = xp[c * 4096];
        float4 w  = sW1T[c];
        a0 = fmaf(xv, w.x, a0);
        a1 = fmaf(xv, w.y, a1);
        a2 = fmaf(xv, w.z, a2);
        a3 = fmaf(xv, w.w, a3);
    }
    float* hp = &g_h1[0][n][0][y][px];
    hp[0]     = fmaxf(a0, 0.f);
    hp[4096]  = fmaxf(a1, 0.f);
    hp[8192]  = fmaxf(a2, 0.f);
    hp[12288] = fmaxf(a3, 0.f);
}

// ---------------------------------------------------------------------------
// chain_kernel (block i):
//   h2_i = relu(conv3x3(h1_i; W2_i) + b2_i)            (halo read from HBM)
//   store h2_i
//   if i<31: h1_{i+1} = relu(W1_{i+1} relu(W3_i h2_i + b3_i) + b1_{i+1})
// Grid 256 CTAs (16 images x 16 tiles of 16x16), 256 threads, 1 px each.
// ---------------------------------------------------------------------------
__global__ __launch_bounds__(256) void chain_kernel(
    const float* __restrict__ w1, const float* __restrict__ b1,
    const float* __restrict__ w2, const float* __restrict__ b2,
    const float* __restrict__ w3, const float* __restrict__ b3,
    int blk)
{
    __shared__ float  s_h1[4][18][18];
    __shared__ float  s_w2[144];      // [j][k][dy][dx] flat
    __shared__ float  s_b2[4];
    __shared__ float4 s_w3[256];      // W3 row per c (contiguous 4 in gmem)
    __shared__ float4 s_w1t[256];     // W1_{blk+1} column per c
    __shared__ float  s_b3[256];
    __shared__ float  s_b1n[4];

    int tid  = threadIdx.x;
    int n    = blockIdx.x >> 4;
    int tile = blockIdx.x & 15;
    int ty0  = (tile >> 2) * 16;
    int tx0  = (tile & 3)  * 16;

    if (tid < 144) s_w2[tid] = w2[blk * 144 + tid];
    if (tid >= 144 && tid < 148) s_b2[tid - 144] = b2[blk * 4 + (tid - 144)];
    if (blk < 31) {
        s_w3[tid] = *(const float4*)&w3[(blk * 256 + tid) * 4];
        const float* w1n = w1 + (blk + 1) * 1024;
        s_w1t[tid] = make_float4(w1n[tid], w1n[256 + tid], w1n[512 + tid], w1n[768 + tid]);
        s_b3[tid]  = b3[blk * 256 + tid];
        if (tid < 4) s_b1n[tid] = b1[(blk + 1) * 4 + tid];
    }

    // load h1 tile + 1-px halo (zero pad = SAME padding of the 3x3 conv)
    const float* h1base = &g_h1[blk & 1][n][0][0][0];
    for (int idx = tid; idx < 324; idx += 256) {
        int yy = idx / 18, xx = idx % 18;
        int gy = ty0 + yy - 1, gx = tx0 + xx - 1;
        bool ok = (gy >= 0 && gy < 64 && gx >= 0 && gx < 64);
#pragma unroll
        for (int k = 0; k < 4; k++)
            s_h1[k][yy][xx] = ok ? h1base[k * 4096 + gy * 64 + gx] : 0.f;
    }
    __syncthreads();

    int xx = tid & 15, yy = tid >> 4;
    float r0 = s_b2[0], r1 = s_b2[1], r2 = s_b2[2], r3 = s_b2[3];
#pragma unroll
    for (int k = 0; k < 4; k++) {
        float v[9];
#pragma unroll
        for (int dy = 0; dy < 3; dy++)
#pragma unroll
            for (int dx = 0; dx < 3; dx++)
                v[dy * 3 + dx] = s_h1[k][yy + dy][xx + dx];
#pragma unroll
        for (int t = 0; t < 9; t++) {
            r0 = fmaf(v[t], s_w2[(0 * 4 + k) * 9 + t], r0);
            r1 = fmaf(v[t], s_w2[(1 * 4 + k) * 9 + t], r1);
            r2 = fmaf(v[t], s_w2[(2 * 4 + k) * 9 + t], r2);
            r3 = fmaf(v[t], s_w2[(3 * 4 + k) * 9 + t], r3);
        }
    }
    float u0 = fmaxf(r0, 0.f), u1 = fmaxf(r1, 0.f);
    float u2 = fmaxf(r2, 0.f), u3 = fmaxf(r3, 0.f);

    int gy = ty0 + yy, gx = tx0 + xx;
    float* h2p = &g_h2[blk][n][0][gy][gx];
    h2p[0] = u0; h2p[4096] = u1; h2p[8192] = u2; h2p[12288] = u3;

    if (blk < 31) {
        float a0 = s_b1n[0], a1 = s_b1n[1], a2 = s_b1n[2], a3 = s_b1n[3];
#pragma unroll 4
        for (int c = 0; c < 256; c++) {
            float4 w3r = s_w3[c];
            float  z   = fmaf(u0, w3r.x, s_b3[c]);
            z = fmaf(u1, w3r.y, z);
            z = fmaf(u2, w3r.z, z);
            z = fmaf(u3, w3r.w, z);
            float  v   = fmaxf(z, 0.f);
            float4 w1c = s_w1t[c];
            a0 = fmaf(v, w1c.x, a0);
            a1 = fmaf(v, w1c.y, a1);
            a2 = fmaf(v, w1c.z, a2);
            a3 = fmaf(v, w1c.w, a3);
        }
        float* hp = &g_h1[(blk + 1) & 1][n][0][gy][gx];
        hp[0]     = fmaxf(a0, 0.f);
        hp[4096]  = fmaxf(a1, 0.f);
        hp[8192]  = fmaxf(a2, 0.f);
        hp[12288] = fmaxf(a3, 0.f);
    }
}

// ---------------------------------------------------------------------------
// acc_kernel: out = sum_i relu(W3_i @ h2_i + b3_i).
// Grid 1024 CTAs (16 images x 64 rows), 256 threads = 64 px x 4 channel groups.
// Each thread keeps 64 channel accumulators in registers for its pixel.
// ---------------------------------------------------------------------------
__global__ __launch_bounds__(256) void acc_kernel(const float* __restrict__ w3,
                                                  const float* __restrict__ b3,
                                                  float* __restrict__ out) {
    __shared__ float4 s_w3[256];
    __shared__ float  s_b3[256];
    __shared__ float  s_u[4][64];

    int tid   = threadIdx.x;
    int n     = blockIdx.x >> 6;
    int y     = blockIdx.x & 63;
    int px    = tid & 63;
    int cg    = tid >> 6;
    int cbase = cg * 64;

    float acc[64];
#pragma unroll
    for (int cc = 0; cc < 64; cc++) acc[cc] = 0.f;

    for (int i = 0; i < 32; i++) {
        __syncthreads();
        s_w3[tid]   = *(const float4*)&w3[(i * 256 + tid) * 4];
        s_b3[tid]   = b3[i * 256 + tid];
        s_u[cg][px] = g_h2[i][n][cg][y][px];
        __syncthreads();

        float u0 = s_u[0][px], u1 = s_u[1][px], u2 = s_u[2][px], u3 = s_u[3][px];
#pragma unroll
        for (int cc = 0; cc < 64; cc++) {
            int    c = cbase + cc;
            float4 w = s_w3[c];
            float  z = fmaf(u0, w.x, s_b3[c]);
            z = fmaf(u1, w.y, z);
            z = fmaf(u2, w.z, z);
            z = fmaf(u3, w.w, z);
            acc[cc] += fmaxf(z, 0.f);
        }
    }

    float* op = out + ((size_t)(n * 256 + cbase) * 64 + y) * 64 + px;
#pragma unroll
    for (int cc = 0; cc < 64; cc++)
        op[(size_t)cc * 4096] = acc[cc];
}

// ---------------------------------------------------------------------------
extern "C" void kernel_launch(void* const* d_in, const int* in_sizes, int n_in,
                              void* d_out, int out_size) {
    const float* x  = (const float*)d_in[0];
    const float* w1 = (const float*)d_in[1];
    const float* b1 = (const float*)d_in[2];
    const float* w2 = (const float*)d_in[3];
    const float* b2 = (const float*)d_in[4];
    const float* w3 = (const float*)d_in[5];
    const float* b3 = (const float*)d_in[6];
    float* out = (float*)d_out;

    k0_kernel<<<256, 256>>>(x, w1, b1);
    for (int i = 0; i < 32; i++)
        chain_kernel<<<256, 256>>>(w1, b1, w2, b2, w3, b3, i);
    acc_kernel<<<1024, 256>>>(w3, b3, out);
}

// round 3
// speedup vs baseline: 1.0169x; 1.0169x over previous
#include <cuda_runtime.h>

typedef unsigned long long ull;

// Chain state: 4-channel fields only. h1 ping-pong, h2 stored per block.
__device__ float g_h1[2][16][4][64][64];   //  2.1 MB
__device__ float g_h2[32][16][4][64][64];  // 33.6 MB

// ---- packed fp32x2 helpers (Blackwell-only; ptxas won't auto-fuse) --------
__device__ __forceinline__ ull ffma2(ull a, ull b, ull c) {
    ull d; asm("fma.rn.f32x2 %0, %1, %2, %3;" : "=l"(d) : "l"(a), "l"(b), "l"(c)); return d;
}
__device__ __forceinline__ ull fadd2(ull a, ull b) {
    ull d; asm("add.rn.f32x2 %0, %1, %2;" : "=l"(d) : "l"(a), "l"(b)); return d;
}
__device__ __forceinline__ ull pack2(float lo, float hi) {
    ull d; asm("mov.b64 %0, {%1, %2};" : "=l"(d) : "f"(lo), "f"(hi)); return d;
}
__device__ __forceinline__ ull dup2(float v) { return pack2(v, v); }
__device__ __forceinline__ ull relu2(ull z) {
    float lo, hi; asm("mov.b64 {%0, %1}, %2;" : "=f"(lo), "=f"(hi) : "l"(z));
    return pack2(fmaxf(lo, 0.f), fmaxf(hi, 0.f));
}
// {hi(a), lo(b)} — middle tap of a 4-wide row segment
__device__ __forceinline__ ull packmid(ull a, ull b) {
    float alo, ahi, blo, bhi;
    asm("mov.b64 {%0, %1}, %2;" : "=f"(alo), "=f"(ahi) : "l"(a));
    asm("mov.b64 {%0, %1}, %2;" : "=f"(blo), "=f"(bhi) : "l"(b));
    return pack2(ahi, blo);
}

// ---------------------------------------------------------------------------
// k0: h1_0 = relu(W1_0 @ x + b1_0).  Memory-bound (reads x, 67MB); scalar OK.
// ---------------------------------------------------------------------------
__global__ __launch_bounds__(256) void k0_kernel(const float* __restrict__ x,
                                                 const float* __restrict__ w1,
                                                 const float* __restrict__ b1) {
    __shared__ float4 sW1T[256];
    __shared__ float  sB1[4];
    int tid = threadIdx.x;
    if (tid < 4) sB1[tid] = b1[tid];
    sW1T[tid] = make_float4(w1[tid], w1[256 + tid], w1[512 + tid], w1[768 + tid]);
    __syncthreads();

    int n  = blockIdx.x >> 4;
    int yg = blockIdx.x & 15;
    int px = tid & 63;
    int y  = yg * 4 + (tid >> 6);

    const float* xp = x + (size_t)n * 256 * 4096 + y * 64 + px;
    float a0 = sB1[0], a1 = sB1[1], a2 = sB1[2], a3 = sB1[3];
#pragma unroll 8
    for (int c = 0; c < 256; c++) {
        float  xv = xp[c * 4096];
        float4 w  = sW1T[c];
        a0 = fmaf(xv, w.x, a0);
        a1 = fmaf(xv, w.y, a1);
        a2 = fmaf(xv, w.z, a2);
        a3 = fmaf(xv, w.w, a3);
    }
    float* hp = &g_h1[0][n][0][y][px];
    hp[0]     = fmaxf(a0, 0.f);
    hp[4096]  = fmaxf(a1, 0.f);
    hp[8192]  = fmaxf(a2, 0.f);
    hp[12288] = fmaxf(a3, 0.f);
}

// ---------------------------------------------------------------------------
// chain_kernel (block i), 2 pixels per thread, everything fp32x2-packed:
//   h2_i = relu(conv3x3(h1_i) + b2_i); store h2_i
//   if i<31: h1_{i+1} = relu(W1_{i+1} relu(W3_i h2_i + b3_i) + b1_{i+1})
// Grid 256 CTAs (16 img x 16 tiles of 16x16), 128 threads = 128 pixel-pairs.
// ---------------------------------------------------------------------------
__global__ __launch_bounds__(128) void chain_kernel(
    const float* __restrict__ w1, const float* __restrict__ b1,
    const float* __restrict__ w2, const float* __restrict__ b2,
    const float* __restrict__ w3, const float* __restrict__ b3,
    int blk)
{
    __shared__ __align__(16) float s_h1[4][18][18];   // halo'd input tile
    __shared__ ull        s_w2d[144];        // dup-packed [j][k][dy][dx]
    __shared__ float      s_b2[4];
    __shared__ ulonglong2 s_w3d[256][2];     // dup-packed W3 rows
    __shared__ ulonglong2 s_w1d[256][2];     // dup-packed W1_{blk+1} cols
    __shared__ ull        s_b3d[256];
    __shared__ float      s_b1n[4];

    int tid  = threadIdx.x;
    int n    = blockIdx.x >> 4;
    int tile = blockIdx.x & 15;
    int ty0  = (tile >> 2) * 16;
    int tx0  = (tile & 3)  * 16;

    // weight staging — 128 threads, so stride loops (144 > 128!)
    for (int i = tid; i < 144; i += 128) s_w2d[i] = dup2(w2[blk * 144 + i]);
    if (tid < 4) s_b2[tid] = b2[blk * 4 + tid];
    if (blk < 31) {
        const float* w1n = w1 + (blk + 1) * 1024;
#pragma unroll
        for (int c = tid; c < 256; c += 128) {
            float4 wr = *(const float4*)&w3[(blk * 256 + c) * 4];
            s_w3d[c][0] = make_ulonglong2(dup2(wr.x), dup2(wr.y));
            s_w3d[c][1] = make_ulonglong2(dup2(wr.z), dup2(wr.w));
            s_w1d[c][0] = make_ulonglong2(dup2(w1n[c]),       dup2(w1n[256 + c]));
            s_w1d[c][1] = make_ulonglong2(dup2(w1n[512 + c]), dup2(w1n[768 + c]));
            s_b3d[c]    = dup2(b3[blk * 256 + c]);
        }
        if (tid < 4) s_b1n[tid] = b1[(blk + 1) * 4 + tid];
    }

    // halo tile load (zero pad = SAME padding)
    const float* h1base = &g_h1[blk & 1][n][0][0][0];
    for (int idx = tid; idx < 324; idx += 128) {
        int yy = idx / 18, xx = idx % 18;
        int gy = ty0 + yy - 1, gx = tx0 + xx - 1;
        bool ok = (gy >= 0 && gy < 64 && gx >= 0 && gx < 64);
#pragma unroll
        for (int k = 0; k < 4; k++)
            s_h1[k][yy][xx] = ok ? h1base[k * 4096 + gy * 64 + gx] : 0.f;
    }
    __syncthreads();

    int yy = tid >> 3;
    int x0 = (tid & 7) * 2;

    // packed conv3x3: both pixels of the pair in the low/high halves
    ull r0 = dup2(s_b2[0]), r1 = dup2(s_b2[1]), r2 = dup2(s_b2[2]), r3 = dup2(s_b2[3]);
#pragma unroll
    for (int k = 0; k < 4; k++) {
#pragma unroll
        for (int dy = 0; dy < 3; dy++) {
            const ull* rowp = (const ull*)&s_h1[k][yy + dy][x0];  // 8B aligned (x0 even, row 72B)
            ull p01 = rowp[0], p23 = rowp[1];
            ull tap0 = p01, tap1 = packmid(p01, p23), tap2 = p23;
            int wi = k * 9 + dy * 3;
            r0 = ffma2(tap0, s_w2d[wi + 0], r0);
            r1 = ffma2(tap0, s_w2d[36 + wi + 0], r1);
            r2 = ffma2(tap0, s_w2d[72 + wi + 0], r2);
            r3 = ffma2(tap0, s_w2d[108 + wi + 0], r3);
            r0 = ffma2(tap1, s_w2d[wi + 1], r0);
            r1 = ffma2(tap1, s_w2d[36 + wi + 1], r1);
            r2 = ffma2(tap1, s_w2d[72 + wi + 1], r2);
            r3 = ffma2(tap1, s_w2d[108 + wi + 1], r3);
            r0 = ffma2(tap2, s_w2d[wi + 2], r0);
            r1 = ffma2(tap2, s_w2d[36 + wi + 2], r1);
            r2 = ffma2(tap2, s_w2d[72 + wi + 2], r2);
            r3 = ffma2(tap2, s_w2d[108 + wi + 2], r3);
        }
    }
    ull u0 = relu2(r0), u1 = relu2(r1), u2 = relu2(r2), u3 = relu2(r3);

    int gy = ty0 + yy, gx = tx0 + x0;
    ull* h2p = (ull*)&g_h2[blk][n][0][gy][gx];   // channel stride = 4096 floats = 2048 ull
    h2p[0] = u0; h2p[2048] = u1; h2p[4096] = u2; h2p[6144] = u3;

    if (blk < 31) {
        ull a0 = dup2(s_b1n[0]), a1 = dup2(s_b1n[1]);
        ull a2 = dup2(s_b1n[2]), a3 = dup2(s_b1n[3]);
#pragma unroll 8
        for (int c = 0; c < 256; c++) {
            ulonglong2 wA = s_w3d[c][0], wB = s_w3d[c][1];
            ull z = ffma2(u0, wA.x, s_b3d[c]);
            z = ffma2(u1, wA.y, z);
            z = ffma2(u2, wB.x, z);
            z = ffma2(u3, wB.y, z);
            ull v = relu2(z);
            ulonglong2 qA = s_w1d[c][0], qB = s_w1d[c][1];
            a0 = ffma2(v, qA.x, a0);
            a1 = ffma2(v, qA.y, a1);
            a2 = ffma2(v, qB.x, a2);
            a3 = ffma2(v, qB.y, a3);
        }
        ull* hp = (ull*)&g_h1[(blk + 1) & 1][n][0][gy][gx];
        hp[0]    = relu2(a0);
        hp[2048] = relu2(a1);
        hp[4096] = relu2(a2);
        hp[6144] = relu2(a3);
    }
}

// ---------------------------------------------------------------------------
// acc_kernel: out = sum_i relu(W3_i @ h2_i + b3_i), fp32x2-packed.
// Grid 1024 (16 img x 64 rows), 256 threads = 32 px-pairs x 8 ch-groups of 32.
// 32 packed accumulators per thread.
// ---------------------------------------------------------------------------
__global__ __launch_bounds__(256) void acc_kernel(const float* __restrict__ w3,
                                                  const float* __restrict__ b3,
                                                  float* __restrict__ out) {
    __shared__ ulonglong2 s_w3d[256][2];
    __shared__ ull        s_b3d[256];
    __shared__ __align__(16) float s_u[4][64];

    int tid   = threadIdx.x;
    int n     = blockIdx.x >> 6;
    int y     = blockIdx.x & 63;
    int pair  = tid & 31;
    int grp   = tid >> 5;
    int px0   = pair * 2;
    int cbase = grp * 32;

    ull acc[32];
#pragma unroll
    for (int cc = 0; cc < 32; cc++) acc[cc] = 0ull;

    for (int i = 0; i < 32; i++) {
        __syncthreads();
        float4 wr = *(const float4*)&w3[(i * 256 + tid) * 4];
        s_w3d[tid][0] = make_ulonglong2(dup2(wr.x), dup2(wr.y));
        s_w3d[tid][1] = make_ulonglong2(dup2(wr.z), dup2(wr.w));
        s_b3d[tid]    = dup2(b3[i * 256 + tid]);
        s_u[tid >> 6][tid & 63] = g_h2[i][n][tid >> 6][y][tid & 63];
        __syncthreads();

        ull u0 = *(const ull*)&s_u[0][px0];
        ull u1 = *(const ull*)&s_u[1][px0];
        ull u2 = *(const ull*)&s_u[2][px0];
        ull u3 = *(const ull*)&s_u[3][px0];
#pragma unroll
        for (int cc = 0; cc < 32; cc++) {
            int c = cbase + cc;
            ulonglong2 wA = s_w3d[c][0], wB = s_w3d[c][1];
            ull z = ffma2(u0, wA.x, s_b3d[c]);
            z = ffma2(u1, wA.y, z);
            z = ffma2(u2, wB.x, z);
            z = ffma2(u3, wB.y, z);
            acc[cc] = fadd2(acc[cc], relu2(z));
        }
    }

#pragma unroll
    for (int cc = 0; cc < 32; cc++) {
        int c = cbase + cc;
        *(ull*)&out[(((size_t)n * 256 + c) * 64 + y) * 64 + px0] = acc[cc];
    }
}

// ---------------------------------------------------------------------------
extern "C" void kernel_launch(void* const* d_in, const int* in_sizes, int n_in,
                              void* d_out, int out_size) {
    const float* x  = (const float*)d_in[0];
    const float* w1 = (const float*)d_in[1];
    const float* b1 = (const float*)d_in[2];
    const float* w2 = (const float*)d_in[3];
    const float* b2 = (const float*)d_in[4];
    const float* w3 = (const float*)d_in[5];
    const float* b3 = (const float*)d_in[6];
    float* out = (float*)d_out;

    k0_kernel<<<256, 256>>>(x, w1, b1);
    for (int i = 0; i < 32; i++)
        chain_kernel<<<256, 128>>>(w1, b1, w2, b2, w3, b3, i);
    acc_kernel<<<1024, 256>>>(w3, b3, out);
}